// round 2
// baseline (speedup 1.0000x reference)
#include <cuda_runtime.h>

#define POOL 7
#define FW 128
#define FC 1024
#define CG (FC / 4)          // 256 float4 channel-groups per pixel
#define CG_HALF (CG / 2)     // 128 per CTA

__global__ __launch_bounds__(128, 8)
void roi_bilinear_kernel(const float* __restrict__ feat,
                         const float* __restrict__ rois,
                         float* __restrict__ out) {
    const int roi = blockIdx.x;                 // 0..511
    const int c   = blockIdx.y * CG_HALF + threadIdx.x;  // float4 channel group 0..255

    // ROI box (float -> int32 truncation matches astype(int32) for non-negative)
    const float4 r = __ldg(((const float4*)rois) + roi);
    const int ymin = (int)r.x;
    const int xmin = (int)r.y;
    const int ymax = (int)r.z;
    const int xmax = (int)r.w;

    const float h = (float)(ymax - ymin + 1);
    const float w = (float)(xmax - xmin + 1);
    const float hs = h / (float)POOL;
    const float ws = w / (float)POOL;
    const int ylim = ymax - ymin;
    const int xlim = xmax - xmin;

    const float4* __restrict__ featv = (const float4*)feat;
    float4* __restrict__ outv = (float4*)out;
    const size_t out_roi_base = (size_t)roi * (POOL * POOL) * CG + c;

    #pragma unroll
    for (int py = 0; py < POOL; ++py) {
        const float sy = (float)py * hs;
        const int y0 = (int)floorf(sy);
        const int y1 = min(y0 + 1, ylim);
        const float fy = sy - (float)y0;

        const size_t row0 = ((size_t)(ymin + y0) * FW + xmin) * CG;  // float4 units
        const size_t row1 = ((size_t)(ymin + y1) * FW + xmin) * CG;

        float4 t_prev, b_prev;
        int prev_x = -1;

        #pragma unroll
        for (int px = 0; px < POOL; ++px) {
            const float sx = (float)px * ws;
            const int x0 = (int)floorf(sx);
            const int x1 = min(x0 + 1, xlim);
            const float fx = sx - (float)x0;

            float4 tl, bl;
            if (x0 == prev_x) {              // uniform branch per CTA
                tl = t_prev; bl = b_prev;
            } else {
                tl = featv[row0 + (size_t)x0 * CG + c];
                bl = featv[row1 + (size_t)x0 * CG + c];
            }
            float4 tr, br;
            if (x1 == x0) {
                tr = tl; br = bl;
            } else {
                tr = featv[row0 + (size_t)x1 * CG + c];
                br = featv[row1 + (size_t)x1 * CG + c];
            }
            prev_x = x1; t_prev = tr; b_prev = br;

            float4 o;
            {
                float top, bot;
                top = tl.x + (tr.x - tl.x) * fx;
                bot = bl.x + (br.x - bl.x) * fx;
                o.x = top + (bot - top) * fy;
                top = tl.y + (tr.y - tl.y) * fx;
                bot = bl.y + (br.y - bl.y) * fx;
                o.y = top + (bot - top) * fy;
                top = tl.z + (tr.z - tl.z) * fx;
                bot = bl.z + (br.z - bl.z) * fx;
                o.z = top + (bot - top) * fy;
                top = tl.w + (tr.w - tl.w) * fx;
                bot = bl.w + (br.w - bl.w) * fx;
                o.w = top + (bot - top) * fy;
            }

            outv[out_roi_base + (size_t)(py * POOL + px) * CG] = o;
        }
    }
}

extern "C" void kernel_launch(void* const* d_in, const int* in_sizes, int n_in,
                              void* d_out, int out_size) {
    const float* feat = (const float*)d_in[0];   // (1,128,128,1024) fp32
    const float* rois = (const float*)d_in[1];   // (512,4) fp32
    float* out = (float*)d_out;                  // (512, 7*7*1024) fp32

    dim3 grid(512, 2);
    roi_bilinear_kernel<<<grid, 128>>>(feat, rois, out);
}

// round 3
// speedup vs baseline: 1.0322x; 1.0322x over previous
#include <cuda_runtime.h>

#define POOL 7
#define FW 128
#define FC 1024
#define CG (FC / 4)          // 256 float4 channel-groups per pixel
#define TPB 128              // threads per CTA (half the channel groups)

__device__ __forceinline__ float4 lerp4(float4 p, float4 q, float f) {
    float4 r;
    r.x = p.x + (q.x - p.x) * f;
    r.y = p.y + (q.y - p.y) * f;
    r.z = p.z + (q.z - p.z) * f;
    r.w = p.w + (q.w - p.w) * f;
    return r;
}

__global__ __launch_bounds__(TPB, 6)
void roi_row_kernel(const float* __restrict__ feat,
                    const float* __restrict__ rois,
                    float* __restrict__ out) {
    const int roi = blockIdx.x;          // 0..511
    const int py  = blockIdx.y;          // 0..6
    const int c   = blockIdx.z * TPB + threadIdx.x;  // 0..255 float4 group

    const float4 r = __ldg(((const float4*)rois) + roi);
    const int ymin = (int)r.x;
    const int xmin = (int)r.y;
    const int ymax = (int)r.z;
    const int xmax = (int)r.w;

    const int ylim = ymax - ymin;
    const int xlim = xmax - xmin;
    const float hs = (float)(ylim + 1) / (float)POOL;
    const float ws = (float)(xlim + 1) / (float)POOL;

    const float sy = (float)py * hs;
    const int y0 = (int)floorf(sy);
    const int y1 = min(y0 + 1, ylim);
    const float fy = sy - (float)y0;

    const float4* __restrict__ featv = (const float4*)feat;
    const size_t row0 = ((size_t)(ymin + y0) * FW + xmin) * CG + c;
    const size_t row1 = ((size_t)(ymin + y1) * FW + xmin) * CG + c;

    // per-px horizontal coords (pure ALU, unrolled into registers)
    int x0[POOL], x1[POOL];
    float fxv[POOL];
    #pragma unroll
    for (int px = 0; px < POOL; ++px) {
        const float sx = (float)px * ws;
        const int a = (int)floorf(sx);
        x0[px] = a;
        x1[px] = min(a + 1, xlim);
        fxv[px] = sx - (float)a;
    }

    // ---- top row: batched independent loads with register dedup ----
    float4 tl[POOL];
    #pragma unroll
    for (int px = 0; px < POOL; ++px) {
        if (px > 0 && x0[px] == x0[px - 1]) tl[px] = tl[px - 1];
        else tl[px] = featv[row0 + (size_t)x0[px] * CG];
    }
    float4 top[POOL];
    #pragma unroll
    for (int px = 0; px < POOL; ++px) {
        float4 tr;
        if (x1[px] == x0[px]) tr = tl[px];
        else if (px < POOL - 1 && x1[px] == x0[px + 1]) tr = tl[px + 1];
        else tr = featv[row0 + (size_t)x1[px] * CG];
        top[px] = lerp4(tl[px], tr, fxv[px]);
    }

    // ---- bottom row ----
    float4 bl[POOL];
    #pragma unroll
    for (int px = 0; px < POOL; ++px) {
        if (px > 0 && x0[px] == x0[px - 1]) bl[px] = bl[px - 1];
        else bl[px] = featv[row1 + (size_t)x0[px] * CG];
    }

    float4* __restrict__ outv = (float4*)out;
    const size_t out_base = ((size_t)roi * (POOL * POOL) + (size_t)py * POOL) * CG + c;

    #pragma unroll
    for (int px = 0; px < POOL; ++px) {
        float4 br;
        if (x1[px] == x0[px]) br = bl[px];
        else if (px < POOL - 1 && x1[px] == x0[px + 1]) br = bl[px + 1];
        else br = featv[row1 + (size_t)x1[px] * CG];
        const float4 bot = lerp4(bl[px], br, fxv[px]);
        outv[out_base + (size_t)px * CG] = lerp4(top[px], bot, fy);
    }
}

extern "C" void kernel_launch(void* const* d_in, const int* in_sizes, int n_in,
                              void* d_out, int out_size) {
    const float* feat = (const float*)d_in[0];   // (1,128,128,1024) fp32
    const float* rois = (const float*)d_in[1];   // (512,4) fp32
    float* out = (float*)d_out;                  // (512, 7*7*1024) fp32

    dim3 grid(512, POOL, 2);
    roi_row_kernel<<<grid, TPB>>>(feat, rois, out);
}

// round 4
// speedup vs baseline: 1.7447x; 1.6902x over previous
#include <cuda_runtime.h>

#define POOL 7
#define FW 128
#define FC 1024
#define CG (FC / 4)          // 256 float4 channel-groups per pixel
#define TPB 128              // each thread handles 2 channel groups

__device__ __forceinline__ float4 bilin4(float4 tl, float4 tr, float4 bl, float4 br,
                                         float fx, float fy) {
    float4 o;
    float top, bot;
    top = tl.x + (tr.x - tl.x) * fx;
    bot = bl.x + (br.x - bl.x) * fx;
    o.x = top + (bot - top) * fy;
    top = tl.y + (tr.y - tl.y) * fx;
    bot = bl.y + (br.y - bl.y) * fx;
    o.y = top + (bot - top) * fy;
    top = tl.z + (tr.z - tl.z) * fx;
    bot = bl.z + (br.z - bl.z) * fx;
    o.z = top + (bot - top) * fy;
    top = tl.w + (tr.w - tl.w) * fx;
    bot = bl.w + (br.w - bl.w) * fx;
    o.w = top + (bot - top) * fy;
    return o;
}

__global__ __launch_bounds__(TPB, 10)
void roi_bilinear_kernel(const float* __restrict__ feat,
                         const float* __restrict__ rois,
                         float* __restrict__ out) {
    const int cell = blockIdx.x;          // 0..48  (py*7+px)
    const int roi  = blockIdx.y;          // 0..511
    const int py = cell / POOL;
    const int px = cell % POOL;

    const float4 r = __ldg(((const float4*)rois) + roi);
    const int ymin = (int)r.x;
    const int xmin = (int)r.y;
    const int ymax = (int)r.z;
    const int xmax = (int)r.w;

    const float h = (float)(ymax - ymin + 1);
    const float w = (float)(xmax - xmin + 1);

    const float sy = (float)py * (h / (float)POOL);
    const float sx = (float)px * (w / (float)POOL);

    const int y0 = (int)floorf(sy);
    const int x0 = (int)floorf(sx);
    const int y1 = min(y0 + 1, ymax - ymin);
    const int x1 = min(x0 + 1, xmax - xmin);

    const float fy = sy - (float)y0;
    const float fx = sx - (float)x0;

    const int gy0 = ymin + y0;
    const int gy1 = ymin + y1;
    const int gx0 = xmin + x0;
    const int gx1 = xmin + x1;

    const float4* __restrict__ featv = (const float4*)feat;
    const size_t b00 = ((size_t)gy0 * FW + gx0) * CG;
    const size_t b01 = ((size_t)gy0 * FW + gx1) * CG;
    const size_t b10 = ((size_t)gy1 * FW + gx0) * CG;
    const size_t b11 = ((size_t)gy1 * FW + gx1) * CG;

    const int c0 = threadIdx.x;          // groups c0 and c0+128
    const int c1 = threadIdx.x + TPB;

    // 8 independent 128-bit loads in flight
    const float4 tl0 = __ldg(featv + b00 + c0);
    const float4 tr0 = __ldg(featv + b01 + c0);
    const float4 bl0 = __ldg(featv + b10 + c0);
    const float4 br0 = __ldg(featv + b11 + c0);
    const float4 tl1 = __ldg(featv + b00 + c1);
    const float4 tr1 = __ldg(featv + b01 + c1);
    const float4 bl1 = __ldg(featv + b10 + c1);
    const float4 br1 = __ldg(featv + b11 + c1);

    const float4 o0 = bilin4(tl0, tr0, bl0, br0, fx, fy);
    const float4 o1 = bilin4(tl1, tr1, bl1, br1, fx, fy);

    float4* __restrict__ outv =
        (float4*)(out + ((size_t)roi * (POOL * POOL) + cell) * FC);
    __stcs(outv + c0, o0);   // streaming store: don't pollute L2
    __stcs(outv + c1, o1);
}

extern "C" void kernel_launch(void* const* d_in, const int* in_sizes, int n_in,
                              void* d_out, int out_size) {
    const float* feat = (const float*)d_in[0];   // (1,128,128,1024) fp32
    const float* rois = (const float*)d_in[1];   // (512,4) fp32
    float* out = (float*)d_out;                  // (512, 7*7*1024) fp32

    dim3 grid(POOL * POOL, 512);
    roi_bilinear_kernel<<<grid, TPB>>>(feat, rois, out);
}

// round 5
// speedup vs baseline: 1.7477x; 1.0017x over previous
#include <cuda_runtime.h>

#define POOL 7
#define FW 128
#define FC 1024
#define CG (FC / 4)          // 256 float4 channel-groups per pixel
#define TPB 128              // each thread handles 2 channel groups

__device__ __forceinline__ float4 bilin4(float4 tl, float4 tr, float4 bl, float4 br,
                                         float fx, float fy) {
    float4 o;
    float top, bot;
    top = tl.x + (tr.x - tl.x) * fx;
    bot = bl.x + (br.x - bl.x) * fx;
    o.x = top + (bot - top) * fy;
    top = tl.y + (tr.y - tl.y) * fx;
    bot = bl.y + (br.y - bl.y) * fx;
    o.y = top + (bot - top) * fy;
    top = tl.z + (tr.z - tl.z) * fx;
    bot = bl.z + (br.z - bl.z) * fx;
    o.z = top + (bot - top) * fy;
    top = tl.w + (tr.w - tl.w) * fx;
    bot = bl.w + (br.w - bl.w) * fx;
    o.w = top + (bot - top) * fy;
    return o;
}

__global__ __launch_bounds__(TPB, 10)
void roi_bilinear_kernel(const float* __restrict__ feat,
                         const float* __restrict__ rois,
                         float* __restrict__ out) {
    const int px  = blockIdx.x;           // 0..6
    const int py  = blockIdx.y;           // 0..6
    const int roi = blockIdx.z;           // 0..511

    const float4 r = __ldg(((const float4*)rois) + roi);
    const int ymin = (int)r.x;
    const int xmin = (int)r.y;
    const int ymax = (int)r.z;
    const int xmax = (int)r.w;

    const float h = (float)(ymax - ymin + 1);
    const float w = (float)(xmax - xmin + 1);

    const float sy = (float)py * (h / (float)POOL);
    const float sx = (float)px * (w / (float)POOL);

    const int y0 = (int)floorf(sy);
    const int x0 = (int)floorf(sx);
    const int y1 = min(y0 + 1, ymax - ymin);
    const int x1 = min(x0 + 1, xmax - xmin);

    const float fy = sy - (float)y0;
    const float fx = sx - (float)x0;

    // Warp-uniform: right column / bottom row contribute nothing when the
    // lerp factor is exactly 0 or the coordinate is clamped to a duplicate.
    const bool needx = (x1 != x0) && (fx != 0.0f);
    const bool needy = (y1 != y0) && (fy != 0.0f);

    const int gy0 = ymin + y0;
    const int gy1 = ymin + y1;
    const int gx0 = xmin + x0;
    const int gx1 = xmin + x1;

    const float4* __restrict__ featv = (const float4*)feat;
    const size_t b00 = ((size_t)gy0 * FW + gx0) * CG;
    const size_t b01 = ((size_t)gy0 * FW + gx1) * CG;
    const size_t b10 = ((size_t)gy1 * FW + gx0) * CG;
    const size_t b11 = ((size_t)gy1 * FW + gx1) * CG;

    const int c0 = threadIdx.x;          // groups c0 and c0+128
    const int c1 = threadIdx.x + TPB;

    // Always-needed top-left pair
    const float4 tl0 = __ldg(featv + b00 + c0);
    const float4 tl1 = __ldg(featv + b00 + c1);

    // Conditionally loaded corners (warp-uniform predicates, no divergence;
    // predicated-off loads consume no L1 wavefronts / L2 bytes)
    float4 tr0 = tl0, tr1 = tl1;
    if (needx) {
        tr0 = __ldg(featv + b01 + c0);
        tr1 = __ldg(featv + b01 + c1);
    }
    float4 bl0 = tl0, bl1 = tl1;
    if (needy) {
        bl0 = __ldg(featv + b10 + c0);
        bl1 = __ldg(featv + b10 + c1);
    }
    float4 br0, br1;
    if (needx && needy) {
        br0 = __ldg(featv + b11 + c0);
        br1 = __ldg(featv + b11 + c1);
    } else if (needy) {       // !needx: br column == bl column
        br0 = bl0; br1 = bl1;
    } else if (needx) {       // !needy: br row == tr row
        br0 = tr0; br1 = tr1;
    } else {
        br0 = tl0; br1 = tl1;
    }

    const float4 o0 = bilin4(tl0, tr0, bl0, br0, fx, fy);
    const float4 o1 = bilin4(tl1, tr1, bl1, br1, fx, fy);

    const int cell = py * POOL + px;
    float4* __restrict__ outv =
        (float4*)(out + ((size_t)roi * (POOL * POOL) + cell) * FC);
    __stcs(outv + c0, o0);   // streaming store: don't pollute L2
    __stcs(outv + c1, o1);
}

extern "C" void kernel_launch(void* const* d_in, const int* in_sizes, int n_in,
                              void* d_out, int out_size) {
    const float* feat = (const float*)d_in[0];   // (1,128,128,1024) fp32
    const float* rois = (const float*)d_in[1];   // (512,4) fp32
    float* out = (float*)d_out;                  // (512, 7*7*1024) fp32

    dim3 grid(POOL, POOL, 512);
    roi_bilinear_kernel<<<grid, TPB>>>(feat, rois, out);
}